// round 15
// baseline (speedup 1.0000x reference)
#include <cuda_runtime.h>
#include <cuda_bf16.h>
#include <math.h>
#include <stdint.h>

#define XDIM 100
#define YDIM 100
#define ZDIM 20
#define NVOX 200000
#define HF 44
#define WF 80
#define PIX 3520
#define NCAM 6
#define DBINS 50
#define KTOT1 28800   // 9 taps * 3200 ci (r1)
#define KTOT2 2304    // 9 taps * 256 ci  (r2)
#define KTOT3 3456    // 27 taps * 128 ci (fu)

// ---------------- scratch (static device allocations) ----------------
__device__ float g_ex[100];
__device__ float g_dbins[50];
__device__ float g_xi[100];
__device__ float g_M[6 * 16];
__device__ float g_K3inv[6 * 9];
__device__ unsigned long long g_bmask[6 * 110];  // per (cam, 32px-block): bit d = any in-grid sample

__device__ float g_fT[(size_t)6 * PIX * 65];   // feats+mask transposed: [cam][pix][c]
__device__ unsigned short g_vfh[(size_t)NVOX * 128];
__device__ unsigned short g_vfl[(size_t)NVOX * 128];
__device__ float g_vol[NVOX * 64];             // [z][y][x][c] fp32
__device__ unsigned short g_projh[(size_t)6 * PIX * 3200];
__device__ unsigned short g_projl[(size_t)6 * PIX * 3200];
__device__ unsigned short g_hbufh[(size_t)6 * PIX * 256];
__device__ unsigned short g_hbufl[(size_t)6 * PIX * 256];

__device__ unsigned short g_wr1h[(size_t)256 * KTOT1];
__device__ unsigned short g_wr1l[(size_t)256 * KTOT1];
__device__ unsigned short g_wr2h[(size_t)256 * KTOT2];
__device__ unsigned short g_wr2l[(size_t)256 * KTOT2];
__device__ unsigned short g_wfuh[(size_t)64 * KTOT3];
__device__ unsigned short g_wful[(size_t)64 * KTOT3];

__device__ __forceinline__ float eluf(float x) { return x > 0.f ? x : expm1f(x); }

__device__ __forceinline__ void split_bf16(float v, unsigned short& h, unsigned short& l) {
    __nv_bfloat16 bh = __float2bfloat16(v);
    float r = v - __bfloat162float(bh);
    __nv_bfloat16 bl = __float2bfloat16(r);
    h = *reinterpret_cast<unsigned short*>(&bh);
    l = *reinterpret_cast<unsigned short*>(&bl);
}
__device__ __forceinline__ float join_bf16(unsigned short h, unsigned short l) {
    __nv_bfloat16 bh = *reinterpret_cast<__nv_bfloat16*>(&h);
    __nv_bfloat16 bl = *reinterpret_cast<__nv_bfloat16*>(&l);
    return __bfloat162float(bh) + __bfloat162float(bl);
}

__device__ __forceinline__ uint32_t smem_u32(const void* p) {
    uint32_t a;
    asm("{ .reg .u64 t; cvta.to.shared.u64 t, %1; cvt.u32.u64 %0, t; }" : "=r"(a) : "l"(p));
    return a;
}
__device__ __forceinline__ void cp16(uint32_t dst, const void* src, int sz) {
    asm volatile("cp.async.cg.shared.global [%0], [%1], 16, %2;"
                 :: "r"(dst), "l"(src), "r"(sz) : "memory");
}
#define CP_COMMIT() asm volatile("cp.async.commit_group;" ::: "memory")
#define CP_WAIT1()  asm volatile("cp.async.wait_group 1;" ::: "memory")
#define CP_WAIT0()  asm volatile("cp.async.wait_group 0;" ::: "memory")

#define LDM_X4(r0, r1, r2, r3, addr) \
    asm volatile("ldmatrix.sync.aligned.m8n8.x4.shared.b16 {%0,%1,%2,%3}, [%4];" \
                 : "=r"(r0), "=r"(r1), "=r"(r2), "=r"(r3) : "r"(addr))

#define MMA_BF16(acc, a, b0v, b1v) \
    asm volatile("mma.sync.aligned.m16n8k16.row.col.f32.bf16.bf16.f32 " \
                 "{%0,%1,%2,%3}, {%4,%5,%6,%7}, {%8,%9}, {%0,%1,%2,%3};" \
                 : "+f"((acc)[0]), "+f"((acc)[1]), "+f"((acc)[2]), "+f"((acc)[3]) \
                 : "r"((a)[0]), "r"((a)[1]), "r"((a)[2]), "r"((a)[3]), "r"(b0v), "r"(b1v))

// ---------------- setup ----------------
__global__ void setup_kernel(const float* __restrict__ K, const float* __restrict__ ext) {
    int t = threadIdx.x;
    for (int i = t; i < 6 * 110; i += 128) g_bmask[i] = 0ull;
    if (t < 100) {
        double c0 = 1.0 / 51.5, c1 = 1.0 / 2.0;
        double lin = c0 + (double)(99 - t) * (c1 - c0) / 99.0;
        g_ex[t] = (float)(1.0 / lin);
    }
    if (t < 50) {
        double c0 = 1.0 / 50.0, c1 = 1.0 / 2.0;
        double lin = c0 + (double)(49 - t) * (c1 - c0) / 49.0;
        g_dbins[t] = (float)(1.0 / lin);
    }
    __syncthreads();
    if (t < 100) {
        float q = 2.0f + (float)t * (51.5f - 2.0f) / 99.0f;
        float qc = fminf(fmaxf(q, g_ex[0]), g_ex[99] - 1e-6f);
        int lo = 0, hi = 99;
        while (lo < hi) { int m = (lo + hi) >> 1; if (g_ex[m] >= qc) hi = m; else lo = m + 1; }
        int k = lo - 1; k = max(0, min(98, k));
        g_xi[t] = (float)k + (qc - g_ex[k]) / (g_ex[k + 1] - g_ex[k] + 1e-12f);
    }
    if (t < 6) {
        double A[4][8];
        for (int r = 0; r < 4; r++)
            for (int c = 0; c < 4; c++) {
                A[r][c] = (double)ext[t * 16 + r * 4 + c];
                A[r][c + 4] = (r == c) ? 1.0 : 0.0;
            }
        for (int col = 0; col < 4; col++) {
            int piv = col; double best = fabs(A[col][col]);
            for (int r = col + 1; r < 4; r++) { double v = fabs(A[r][col]); if (v > best) { best = v; piv = r; } }
            if (piv != col) for (int c = 0; c < 8; c++) { double tmp = A[col][c]; A[col][c] = A[piv][c]; A[piv][c] = tmp; }
            double d = A[col][col];
            for (int c = 0; c < 8; c++) A[col][c] /= d;
            for (int r = 0; r < 4; r++) if (r != col) {
                double f = A[r][col];
                for (int c = 0; c < 8; c++) A[r][c] -= f * A[col][c];
            }
        }
        for (int r = 0; r < 4; r++)
            for (int c = 0; c < 4; c++) {
                double s = 0;
                for (int k2 = 0; k2 < 4; k2++) s += (double)K[t * 16 + r * 4 + k2] * A[k2][c + 4];
                g_M[t * 16 + r * 4 + c] = (float)s;
            }
        double a00 = K[t*16+0], a01 = K[t*16+1], a02 = K[t*16+2];
        double a10 = K[t*16+4], a11 = K[t*16+5], a12 = K[t*16+6];
        double a20 = K[t*16+8], a21 = K[t*16+9], a22 = K[t*16+10];
        double det = a00*(a11*a22 - a12*a21) - a01*(a10*a22 - a12*a20) + a02*(a10*a21 - a11*a20);
        double id = 1.0 / det;
        g_K3inv[t*9+0] = (float)((a11*a22 - a12*a21) * id);
        g_K3inv[t*9+1] = (float)((a02*a21 - a01*a22) * id);
        g_K3inv[t*9+2] = (float)((a01*a12 - a02*a11) * id);
        g_K3inv[t*9+3] = (float)((a12*a20 - a10*a22) * id);
        g_K3inv[t*9+4] = (float)((a00*a22 - a02*a20) * id);
        g_K3inv[t*9+5] = (float)((a02*a10 - a00*a12) * id);
        g_K3inv[t*9+6] = (float)((a10*a21 - a11*a20) * id);
        g_K3inv[t*9+7] = (float)((a01*a20 - a00*a21) * id);
        g_K3inv[t*9+8] = (float)((a00*a11 - a01*a10) * id);
    }
}

// ---------------- feats transpose: [cam][c][pix] -> [cam][pix][65] ----------------
__global__ void ftrans_kernel(const float* __restrict__ feats, const float* __restrict__ masks) {
    int idx = blockIdx.x * blockDim.x + threadIdx.x;
    int total = 6 * 65 * PIX;
    if (idx >= total) return;
    int cam = idx / (65 * PIX);
    int r = idx % (65 * PIX);
    int c = r / PIX, p = r % PIX;
    float v = (c < 64) ? feats[(cam * 64 + c) * PIX + p] : masks[cam * PIX + p];
    g_fT[(size_t)(cam * PIX + p) * 65 + c] = v;
}

// ---------------- r1 weight prep ----------------
__global__ void wprep_r1(const float* __restrict__ w) {
    int total = 256 * 3200 * 9;
    for (int idx = blockIdx.x * blockDim.x + threadIdx.x; idx < total; idx += gridDim.x * blockDim.x) {
        int co = idx / (3200 * 9);
        int r = idx % (3200 * 9);
        int ci_ref = r / 9, tap = r % 9;
        int c = ci_ref / 50, d = ci_ref % 50;
        unsigned short h, l;
        split_bf16(w[idx], h, l);
        size_t dst = (size_t)co * KTOT1 + tap * 3200 + d * 64 + c;
        g_wr1h[dst] = h;
        g_wr1l[dst] = l;
    }
}

// ---------------- generic weight prep ----------------
__global__ void wprep_gen(const float* __restrict__ w, int which, int CO, int CI, int TAPS) {
    unsigned short* dh = (which == 1) ? g_wr2h : g_wfuh;
    unsigned short* dl = (which == 1) ? g_wr2l : g_wful;
    int KT = CI * TAPS;
    int total = CO * KT;
    for (int idx = blockIdx.x * blockDim.x + threadIdx.x; idx < total; idx += gridDim.x * blockDim.x) {
        int co = idx / KT;
        int r = idx % KT;
        int ci = r / TAPS, tap = r % TAPS;
        unsigned short h, l;
        split_bf16(w[idx], h, l);
        size_t dst = (size_t)co * KT + tap * CI + ci;
        dh[dst] = h;
        dl[dst] = l;
    }
}

// ---------------- fused backproj + voxel MLP ----------------
#define CAT_STRIDE 133
#define FUSED_SMEM 152616

__global__ __launch_bounds__(128) void bpmlp_kernel(const float* __restrict__ w_ov, const float* __restrict__ b_ov,
                                                    const float* __restrict__ w_no, const float* __restrict__ b_no) {
    extern __shared__ float sm[];
    float* wovS = sm;
    float* wnoS = wovS + 8320;
    float* catS = wnoS + 4160;
    int*   cntS = (int*)(catS + 130 * CAT_STRIDE);
    unsigned short* sh = (unsigned short*)(cntS + 128);
    unsigned short* sl = sh + 64 * 129;
    int t = threadIdx.x, lane = t & 31, w = t >> 5;
    int n0 = blockIdx.x * 128;

    for (int i = t; i < 8320; i += 128) wovS[i] = w_ov[i];
    for (int i = t; i < 4160; i += 128) wnoS[i] = w_no[i];

    for (int v = 0; v < 32; v++) {
        int col = w * 32 + v;
        int n = n0 + col;
        bool nv = n < NVOX;
        int ncl = nv ? n : 0;
        int z = ncl / 10000, y = (ncl / 100) % 100, x = ncl % 100;
        float gx = g_ex[x];
        float gy = -25.0f + 0.5f * (float)y;
        float gz = -3.0f + (float)z * (5.7f / 19.0f);
        float accg[2][3];
#pragma unroll
        for (int g2 = 0; g2 < 2; g2++)
#pragma unroll
            for (int j = 0; j < 3; j++) accg[g2][j] = 0.f;
        int cnt = 0;
#pragma unroll
        for (int cam = 0; cam < 6; cam++) {
            const float* Mc = &g_M[cam * 16];
            float px = Mc[0]*gx + Mc[1]*gy + Mc[2]*gz + Mc[3];
            float py = Mc[4]*gx + Mc[5]*gy + Mc[6]*gz + Mc[7];
            float pz = Mc[8]*gx + Mc[9]*gy + Mc[10]*gz + Mc[11];
            float zd = pz + 1e-8f;
            float u = px / zd, vv = py / zd;
            bool ok = (pz > 1e-8f) && (u >= 0.f) && (u <= 79.f) && (vv >= 0.f) && (vv <= 43.f);
            if (ok) {
                cnt++;
                float fu = floorf(u), fv = floorf(vv);
                float du = u - fu, dv = vv - fv;
                int u0 = min(max((int)fu, 0), 79); int u1 = min(u0 + 1, 79);
                int v0 = min(max((int)fv, 0), 43); int v1 = min(v0 + 1, 43);
                float w00 = (1 - du) * (1 - dv), w01 = du * (1 - dv);
                float w10 = (1 - du) * dv,       w11 = du * dv;
                const float* F = g_fT + (size_t)(cam * PIX) * 65;
                const float* F00 = F + (size_t)(v0 * 80 + u0) * 65;
                const float* F01 = F + (size_t)(v0 * 80 + u1) * 65;
                const float* F10 = F + (size_t)(v1 * 80 + u0) * 65;
                const float* F11 = F + (size_t)(v1 * 80 + u1) * 65;
                int g2 = cam >= 3;
#pragma unroll
                for (int j = 0; j < 3; j++) {
                    int c = j * 32 + lane;
                    if (c < 65) {
                        float val = w00 * __ldg(F00 + c) + w01 * __ldg(F01 + c)
                                  + w10 * __ldg(F10 + c) + w11 * __ldg(F11 + c);
                        accg[g2][j] += val;
                    }
                }
            }
        }
#pragma unroll
        for (int g2 = 0; g2 < 2; g2++)
#pragma unroll
            for (int j = 0; j < 3; j++) {
                int c = j * 32 + lane;
                if (c < 65) catS[(g2 * 65 + c) * CAT_STRIDE + col] = accg[g2][j];
            }
        if (lane == 0) cntS[col] = nv ? cnt : 0;
    }
    __syncthreads();

    int n = n0 + t;
    int cnt = cntS[t];
    if (cnt == 1 || cnt == 2) {
        float fo = (cnt == 2) ? 1.f : 0.f;
        float fn = (cnt == 1) ? 1.f : 0.f;
        for (int co = 0; co < 64; co++) {
            float av = b_ov[co], an = b_no[co];
            const float* wov = &wovS[co * 130];
            const float* wno = &wnoS[co * 65];
#pragma unroll 5
            for (int k = 0; k < 65; k++) {
                float cl = catS[k * CAT_STRIDE + t];
                float ch = catS[(k + 65) * CAT_STRIDE + t];
                av = fmaf(wov[k], cl, av);
                av = fmaf(wov[65 + k], ch, av);
                an = fmaf(wno[k], cl + ch, an);
            }
            float vv = fo * eluf(av) + fn * eluf(an);
            unsigned short h, l;
            split_bf16(vv, h, l);
            sh[co * 129 + t] = h;
            sl[co * 129 + t] = l;
        }
    } else {
        for (int co = 0; co < 64; co++) { sh[co * 129 + t] = 0; sl[co * 129 + t] = 0; }
    }
    __syncthreads();
    for (int i = t; i < 128 * 64; i += 128) {
        int v = i >> 6, c = i & 63;
        int nn = n0 + v;
        if (nn < NVOX) {
            size_t d = (size_t)nn * 128 + c;
            g_vfh[d] = sh[c * 129 + v];
            g_vfl[d] = sl[c * 129 + v];
        }
    }
}

// ---------------- x remap: fill c=64..127 of [voxel][c] ----------------
__global__ __launch_bounds__(256) void remap_kernel() {
    int t = threadIdx.x;
    int c = t & 63, vq = t >> 6;
    int n = blockIdx.x * 4 + vq;
    if (n >= NVOX) return;
    int x = n % 100;
    float xi = g_xi[x];
    float f = floorf(xi);
    float tx = xi - f;
    int a = min(max((int)f, 0), 99);
    int b2 = min(a + 1, 99);
    size_t rowbase = (size_t)(n - x) * 128;
    float va = join_bf16(g_vfh[rowbase + (size_t)a * 128 + c], g_vfl[rowbase + (size_t)a * 128 + c]);
    float vb = join_bf16(g_vfh[rowbase + (size_t)b2 * 128 + c], g_vfl[rowbase + (size_t)b2 * 128 + c]);
    float v = va * (1.f - tx) + vb * tx;
    unsigned short h, l;
    split_bf16(v, h, l);
    size_t d = (size_t)n * 128 + 64 + c;
    g_vfh[d] = h;
    g_vfl[d] = l;
}

// ---------------- conv3d HMMA: M=128 vox, N=64 co, K=3456 ----------------
#define C3_NSTG 3
#define C3_STG  49152
#define C3_AH   0
#define C3_AL   16384
#define C3_BH   32768
#define C3_BL   40960
#define C3_SMEM (C3_NSTG * C3_STG)

__global__ __launch_bounds__(256, 1) void conv3d_hmma(const float* __restrict__ bias) {
    extern __shared__ char smem[];
    uint32_t sb = smem_u32(smem);
    int t = threadIdx.x, lane = t & 31, wid = t >> 5;
    int n0 = blockIdx.x * 128;

    int rA = t & 127, half = t >> 7;
    int nA = n0 + rA;
    bool pvalid = nA < NVOX;
    int ncl = min(nA, NVOX - 1);
    int zA = ncl / 10000, yA = (ncl / 100) % 100, xA = ncl % 100;

    int rowB = t >> 2, jb = (t & 3) * 2;

    int wm = wid & 3, wn = wid >> 2;
    int m_base = wm * 32, n_base = wn * 32;

    float acc[2][4][4];
#pragma unroll
    for (int a = 0; a < 2; a++)
#pragma unroll
        for (int b = 0; b < 4; b++)
#pragma unroll
            for (int c = 0; c < 4; c++) acc[a][b][c] = 0.f;

    auto issue = [&](int ch) {
        int s = ch % C3_NSTG;
        uint32_t st = sb + s * C3_STG;
        int tap = ch >> 1, ci0 = (ch & 1) * 64;
        int dz = tap / 9 - 1, dy = (tap / 3) % 3 - 1, dx = tap % 3 - 1;
        int z2 = zA + dz, y2 = yA + dy, x2 = xA + dx;
        bool ok = pvalid && ((unsigned)z2 < 20u) && ((unsigned)y2 < 100u) && ((unsigned)x2 < 100u);
        size_t abase = ok ? ((size_t)((z2 * 100 + y2) * 100 + x2) * 128 + ci0 + half * 32)
                          : (size_t)(ci0 + half * 32);
        int sz = ok ? 16 : 0;
#pragma unroll
        for (int j = 0; j < 4; j++) {
            uint32_t off = (uint32_t)rA * 128 + half * 64 + j * 16;
            off ^= (off >> 3) & 0x70;
            cp16(st + C3_AH + off, g_vfh + abase + j * 8, sz);
            cp16(st + C3_AL + off, g_vfl + abase + j * 8, sz);
        }
        size_t bbase = (size_t)rowB * KTOT3 + tap * 128 + ci0;
#pragma unroll
        for (int jj = 0; jj < 2; jj++) {
            int j = jb + jj;
            uint32_t off = (uint32_t)rowB * 128 + j * 16;
            off ^= (off >> 3) & 0x70;
            cp16(st + C3_BH + off, g_wfuh + bbase + j * 8, 16);
            cp16(st + C3_BL + off, g_wful + bbase + j * 8, 16);
        }
        CP_COMMIT();
    };

    issue(0);
    issue(1);

    for (int ch = 0; ch < 54; ch++) {
        int s = ch % C3_NSTG;
        if (ch + 1 < 54) CP_WAIT1(); else CP_WAIT0();
        __syncthreads();
        if (ch + 2 < 54) issue(ch + 2);

        uint32_t st = sb + s * C3_STG;
        int arow = m_base + (lane & 15);
        int acolx = (lane & 16);
        int brow = n_base + (lane & 7) + ((lane & 16) >> 1);
        int bcolx = (lane & 8) << 1;
#pragma unroll
        for (int ks = 0; ks < 4; ks++) {
            uint32_t aH[2][4], aL[2][4], bH[4][2], bL[4][2];
#pragma unroll
            for (int mf = 0; mf < 2; mf++) {
                uint32_t off = (uint32_t)(arow + mf * 16) * 128 + ks * 32 + acolx;
                off ^= (off >> 3) & 0x70;
                LDM_X4(aH[mf][0], aH[mf][1], aH[mf][2], aH[mf][3], st + C3_AH + off);
                LDM_X4(aL[mf][0], aL[mf][1], aL[mf][2], aL[mf][3], st + C3_AL + off);
            }
#pragma unroll
            for (int np = 0; np < 2; np++) {
                uint32_t off = (uint32_t)(brow + np * 16) * 128 + ks * 32 + bcolx;
                off ^= (off >> 3) & 0x70;
                uint32_t r0, r1, r2, r3;
                LDM_X4(r0, r1, r2, r3, st + C3_BH + off);
                bH[np * 2][0] = r0; bH[np * 2][1] = r1;
                bH[np * 2 + 1][0] = r2; bH[np * 2 + 1][1] = r3;
                LDM_X4(r0, r1, r2, r3, st + C3_BL + off);
                bL[np * 2][0] = r0; bL[np * 2][1] = r1;
                bL[np * 2 + 1][0] = r2; bL[np * 2 + 1][1] = r3;
            }
#pragma unroll
            for (int mf = 0; mf < 2; mf++)
#pragma unroll
                for (int nf = 0; nf < 4; nf++) {
                    MMA_BF16(acc[mf][nf], aH[mf], bH[nf][0], bH[nf][1]);
                    MMA_BF16(acc[mf][nf], aH[mf], bL[nf][0], bL[nf][1]);
                    MMA_BF16(acc[mf][nf], aL[mf], bH[nf][0], bH[nf][1]);
                }
        }
        __syncthreads();
    }

#pragma unroll
    for (int nf = 0; nf < 4; nf++) {
        int c = n_base + nf * 8 + (lane & 3) * 2;
        float bb0 = __ldg(bias + c), bb1 = __ldg(bias + c + 1);
#pragma unroll
        for (int mf = 0; mf < 2; mf++) {
            int nn = n0 + m_base + mf * 16 + (lane >> 2);
            if (nn < NVOX) {
                g_vol[(size_t)nn * 64 + c] = eluf(acc[mf][nf][0] + bb0);
                g_vol[(size_t)nn * 64 + c + 1] = eluf(acc[mf][nf][1] + bb1);
            }
            if (nn + 8 < NVOX) {
                g_vol[(size_t)(nn + 8) * 64 + c] = eluf(acc[mf][nf][2] + bb0);
                g_vol[(size_t)(nn + 8) * 64 + c + 1] = eluf(acc[mf][nf][3] + bb1);
            }
        }
    }
}

// ---------------- frustum sampling (+ 32px-block occupancy mask) ----------------
__global__ __launch_bounds__(256) void sample_kernel(const float* __restrict__ ext) {
    __shared__ float exs[100];
    __shared__ int anyin;
    int t = threadIdx.x;
    if (t < 100) exs[t] = g_ex[t];
    if (t == 0) anyin = 0;
    __syncthreads();
    int cam = blockIdx.z, d = blockIdx.y, p0 = blockIdx.x * 32;
    int wrp = t >> 5, lane = t & 31;
    float dep = g_dbins[d];
    const float* Ki = &g_K3inv[cam * 9];
    const float* E = ext + cam * 16;
#pragma unroll
    for (int i = 0; i < 4; i++) {
        int p = p0 + wrp * 4 + i;
        float u = (float)(p % 80), v = (float)(p / 80);
        float cx = (Ki[0] * u + Ki[1] * v + Ki[2]) * dep;
        float cy = (Ki[3] * u + Ki[4] * v + Ki[5]) * dep;
        float cz = (Ki[6] * u + Ki[7] * v + Ki[8]) * dep;
        float wx = E[0] * cx + E[1] * cy + E[2] * cz + E[3];
        float wy = E[4] * cx + E[5] * cy + E[6] * cz + E[7];
        float wz = E[8] * cx + E[9] * cy + E[10] * cz + E[11];
        float yi = (wy - (-25.0f)) / 49.5f * 99.0f;
        float zi = (wz - (-3.0f)) / 5.7f * 19.0f;
        bool inb = (wx >= 2.0f) && (wx <= 51.5f) && (yi >= 0.f) && (yi <= 99.f) && (zi >= 0.f) && (zi <= 19.f);
        float v0 = 0.f, v1 = 0.f;
        if (inb) {
            if (lane == 0) anyin = 1;
            float qc = fminf(fmaxf(wx, exs[0]), exs[99] - 1e-6f);
            int lo = 0, hi = 99;
            while (lo < hi) { int m = (lo + hi) >> 1; if (exs[m] >= qc) hi = m; else lo = m + 1; }
            int k = max(0, min(98, lo - 1));
            float xi = (float)k + (qc - exs[k]) / (exs[k + 1] - exs[k] + 1e-12f);
            float fx = floorf(xi), fy = floorf(yi), fz = floorf(zi);
            float tx = xi - fx, ty = yi - fy, tz = zi - fz;
            int x0 = min(max((int)fx, 0), 99), x1 = min(x0 + 1, 99);
            int y0 = min(max((int)fy, 0), 99), y1 = min(y0 + 1, 99);
            int z0 = min(max((int)fz, 0), 19), z1 = min(z0 + 1, 19);
            float w000 = (1 - tx) * (1 - ty) * (1 - tz), w100 = tx * (1 - ty) * (1 - tz);
            float w010 = (1 - tx) * ty * (1 - tz),       w110 = tx * ty * (1 - tz);
            float w001 = (1 - tx) * (1 - ty) * tz,       w101 = tx * (1 - ty) * tz;
            float w011 = (1 - tx) * ty * tz,             w111 = tx * ty * tz;
            int b000 = ((z0 * 100 + y0) * 100 + x0) * 64;
            int b100 = ((z0 * 100 + y0) * 100 + x1) * 64;
            int b010 = ((z0 * 100 + y1) * 100 + x0) * 64;
            int b110 = ((z0 * 100 + y1) * 100 + x1) * 64;
            int b001 = ((z1 * 100 + y0) * 100 + x0) * 64;
            int b101 = ((z1 * 100 + y0) * 100 + x1) * 64;
            int b011 = ((z1 * 100 + y1) * 100 + x0) * 64;
            int b111 = ((z1 * 100 + y1) * 100 + x1) * 64;
            const float* V = g_vol;
            v0 = w000 * V[b000 + lane] + w100 * V[b100 + lane]
               + w010 * V[b010 + lane] + w110 * V[b110 + lane]
               + w001 * V[b001 + lane] + w101 * V[b101 + lane]
               + w011 * V[b011 + lane] + w111 * V[b111 + lane];
            int l2 = lane + 32;
            v1 = w000 * V[b000 + l2] + w100 * V[b100 + l2]
               + w010 * V[b010 + l2] + w110 * V[b110 + l2]
               + w001 * V[b001 + l2] + w101 * V[b101 + l2]
               + w011 * V[b011 + l2] + w111 * V[b111 + l2];
        }
        unsigned short h0, l0, h1, l1;
        split_bf16(v0, h0, l0);
        split_bf16(v1, h1, l1);
        size_t base = ((size_t)(cam * PIX + p)) * 3200 + (size_t)d * 64;
        g_projh[base + lane] = h0;        g_projl[base + lane] = l0;
        g_projh[base + 32 + lane] = h1;   g_projl[base + 32 + lane] = l1;
    }
    __syncthreads();
    if (t == 0 && anyin)
        atomicOr(&g_bmask[cam * 110 + blockIdx.x], 1ull << d);
}

// ---------------- conv r1 HMMA: M=128 pix x N=128 co, sparse d-chunks, tap-inner ----------------
#define R1_NSTG 3
#define R1_STG  65536
#define R1_AH   0
#define R1_AL   16384
#define R1_BH   32768
#define R1_BL   49152
#define R1_SMEM (R1_NSTG * R1_STG)

__global__ __launch_bounds__(256, 1) void conv_r1_sparse(const float* __restrict__ bias) {
    extern __shared__ char smem[];
    __shared__ unsigned char dlist[56];
    __shared__ int dcnt_s;
    uint32_t sb = smem_u32(smem);
    int t = threadIdx.x, lane = t & 31, wid = t >> 5;
    int cam = blockIdx.z;
    int co0 = blockIdx.y * 128;
    int p0 = blockIdx.x * 128;

    if (t == 0) {
        int blo = max(0, (p0 - 81) >> 5);
        int bhi = min(109, (p0 + 208) >> 5);
        unsigned long long m = 0ull;
        for (int b = blo; b <= bhi; b++) m |= g_bmask[cam * 110 + b];
        int c = 0;
        for (int d = 0; d < 50; d++)
            if ((m >> d) & 1) dlist[c++] = (unsigned char)d;
        dcnt_s = c;
    }
    __syncthreads();
    int dcnt = dcnt_s;
    int nact = dcnt * 9;

    const unsigned short* inH = g_projh + (size_t)cam * PIX * 3200;
    const unsigned short* inL = g_projl + (size_t)cam * PIX * 3200;

    int rA = t & 127, half = t >> 7;
    int pA = p0 + rA;
    int ypix = pA / 80, xpix = pA % 80;
    bool pvalid = pA < PIX;

    int wm = wid & 1, wn = wid >> 1;
    int m_base = wm * 64, n_base = wn * 32;

    float acc[4][4][4];
#pragma unroll
    for (int a = 0; a < 4; a++)
#pragma unroll
        for (int b = 0; b < 4; b++)
#pragma unroll
            for (int c = 0; c < 4; c++) acc[a][b][c] = 0.f;

    auto issue = [&](int li) {
        int s = li % R1_NSTG;
        uint32_t st = sb + s * R1_STG;
        // d-outer / tap-inner: 9 consecutive chunks reuse the same proj rows (±1 px shifts)
        int di = li / 9;
        int tap = li - di * 9;
        int dd = dlist[di];
        int ci0 = dd * 64;
        int dy = tap / 3 - 1, dx = tap % 3 - 1;
        int y2 = ypix + dy, x2 = xpix + dx;
        bool ok = pvalid && ((unsigned)y2 < 44u) && ((unsigned)x2 < 80u);
        size_t abase = ok ? (((size_t)(y2 * 80 + x2)) * 3200 + ci0 + half * 32)
                          : (size_t)(ci0 + half * 32);
        int sz = ok ? 16 : 0;
#pragma unroll
        for (int j = 0; j < 4; j++) {
            uint32_t off = (uint32_t)rA * 128 + half * 64 + j * 16;
            off ^= (off >> 3) & 0x70;
            cp16(st + R1_AH + off, inH + abase + j * 8, sz);
            cp16(st + R1_AL + off, inL + abase + j * 8, sz);
        }
        size_t bbase = (size_t)(co0 + rA) * KTOT1 + tap * 3200 + ci0 + half * 32;
#pragma unroll
        for (int j = 0; j < 4; j++) {
            uint32_t off = (uint32_t)rA * 128 + half * 64 + j * 16;
            off ^= (off >> 3) & 0x70;
            cp16(st + R1_BH + off, g_wr1h + bbase + j * 8, 16);
            cp16(st + R1_BL + off, g_wr1l + bbase + j * 8, 16);
        }
        CP_COMMIT();
    };

    if (nact > 0) issue(0);
    if (nact > 1) issue(1);

    for (int ch = 0; ch < nact; ch++) {
        int s = ch % R1_NSTG;
        if (ch + 1 < nact) CP_WAIT1(); else CP_WAIT0();
        __syncthreads();
        if (ch + 2 < nact) issue(ch + 2);

        uint32_t st = sb + s * R1_STG;
        int arow = m_base + (lane & 15);
        int acolx = (lane & 16);
        int brow = n_base + (lane & 7) + ((lane & 16) >> 1);
        int bcolx = (lane & 8) << 1;
#pragma unroll
        for (int ks = 0; ks < 4; ks++) {
            uint32_t aH[4][4], aL[4][4], bH[4][2], bL[4][2];
#pragma unroll
            for (int mf = 0; mf < 4; mf++) {
                uint32_t off = (uint32_t)(arow + mf * 16) * 128 + ks * 32 + acolx;
                off ^= (off >> 3) & 0x70;
                LDM_X4(aH[mf][0], aH[mf][1], aH[mf][2], aH[mf][3], st + R1_AH + off);
                LDM_X4(aL[mf][0], aL[mf][1], aL[mf][2], aL[mf][3], st + R1_AL + off);
            }
#pragma unroll
            for (int np = 0; np < 2; np++) {
                uint32_t off = (uint32_t)(brow + np * 16) * 128 + ks * 32 + bcolx;
                off ^= (off >> 3) & 0x70;
                uint32_t r0, r1, r2, r3;
                LDM_X4(r0, r1, r2, r3, st + R1_BH + off);
                bH[np * 2][0] = r0; bH[np * 2][1] = r1;
                bH[np * 2 + 1][0] = r2; bH[np * 2 + 1][1] = r3;
                LDM_X4(r0, r1, r2, r3, st + R1_BL + off);
                bL[np * 2][0] = r0; bL[np * 2][1] = r1;
                bL[np * 2 + 1][0] = r2; bL[np * 2 + 1][1] = r3;
            }
#pragma unroll
            for (int mf = 0; mf < 4; mf++)
#pragma unroll
                for (int nf = 0; nf < 4; nf++) {
                    MMA_BF16(acc[mf][nf], aH[mf], bH[nf][0], bH[nf][1]);
                    MMA_BF16(acc[mf][nf], aH[mf], bL[nf][0], bL[nf][1]);
                    MMA_BF16(acc[mf][nf], aL[mf], bH[nf][0], bH[nf][1]);
                }
        }
        __syncthreads();
    }

    // epilogue: bias + elu -> bf16 hi/lo hbuf [cam][pix][co]
#pragma unroll
    for (int nf = 0; nf < 4; nf++) {
        int co = co0 + n_base + nf * 8 + (lane & 3) * 2;
        float bb0 = __ldg(bias + co), bb1 = __ldg(bias + co + 1);
#pragma unroll
        for (int mf = 0; mf < 4; mf++) {
            int pix = p0 + m_base + mf * 16 + (lane >> 2);
#pragma unroll
            for (int q = 0; q < 2; q++) {
                int px = pix + q * 8;
                if (px < PIX) {
                    float v0 = eluf(acc[mf][nf][q * 2] + bb0);
                    float v1 = eluf(acc[mf][nf][q * 2 + 1] + bb1);
                    unsigned short h0, l0, h1, l1;
                    split_bf16(v0, h0, l0);
                    split_bf16(v1, h1, l1);
                    size_t d = ((size_t)cam * PIX + px) * 256 + co;
                    *reinterpret_cast<ushort2*>(&g_hbufh[d]) = make_ushort2(h0, h1);
                    *reinterpret_cast<ushort2*>(&g_hbufl[d]) = make_ushort2(l0, l1);
                }
            }
        }
    }
}

// ---------------- conv r2 HMMA: M=128 pix x N=128 co, dense, fp32 out ----------------
#define R2_NSTG 3
#define R2_STG  65536
#define R2_AH   0
#define R2_AL   16384
#define R2_BH   32768
#define R2_BL   49152
#define R2_SMEM (R2_NSTG * R2_STG)

__global__ __launch_bounds__(256, 1) void conv_r2_hmma(const float* __restrict__ bias, float* __restrict__ outF) {
    extern __shared__ char smem[];
    uint32_t sb = smem_u32(smem);
    int t = threadIdx.x, lane = t & 31, wid = t >> 5;
    int cam = blockIdx.z;
    int co0 = blockIdx.y * 128;
    int p0 = blockIdx.x * 128;

    const unsigned short* inH = g_hbufh + (size_t)cam * PIX * 256;
    const unsigned short* inL = g_hbufl + (size_t)cam * PIX * 256;

    int rA = t & 127, half = t >> 7;
    int pA = p0 + rA;
    int ypix = pA / 80, xpix = pA % 80;
    bool pvalid = pA < PIX;

    int wm = wid & 1, wn = wid >> 1;
    int m_base = wm * 64, n_base = wn * 32;

    float acc[4][4][4];
#pragma unroll
    for (int a = 0; a < 4; a++)
#pragma unroll
        for (int b = 0; b < 4; b++)
#pragma unroll
            for (int c = 0; c < 4; c++) acc[a][b][c] = 0.f;

    auto issue = [&](int ch) {
        int s = ch % R2_NSTG;
        uint32_t st = sb + s * R2_STG;
        int tap = ch >> 2, ci0 = (ch & 3) * 64;
        int dy = tap / 3 - 1, dx = tap % 3 - 1;
        int y2 = ypix + dy, x2 = xpix + dx;
        bool ok = pvalid && ((unsigned)y2 < 44u) && ((unsigned)x2 < 80u);
        size_t abase = ok ? (((size_t)(y2 * 80 + x2)) * 256 + ci0 + half * 32)
                          : (size_t)(ci0 + half * 32);
        int sz = ok ? 16 : 0;
#pragma unroll
        for (int j = 0; j < 4; j++) {
            uint32_t off = (uint32_t)rA * 128 + half * 64 + j * 16;
            off ^= (off >> 3) & 0x70;
            cp16(st + R2_AH + off, inH + abase + j * 8, sz);
            cp16(st + R2_AL + off, inL + abase + j * 8, sz);
        }
        size_t bbase = (size_t)(co0 + rA) * KTOT2 + tap * 256 + ci0 + half * 32;
#pragma unroll
        for (int j = 0; j < 4; j++) {
            uint32_t off = (uint32_t)rA * 128 + half * 64 + j * 16;
            off ^= (off >> 3) & 0x70;
            cp16(st + R2_BH + off, g_wr2h + bbase + j * 8, 16);
            cp16(st + R2_BL + off, g_wr2l + bbase + j * 8, 16);
        }
        CP_COMMIT();
    };

    issue(0);
    issue(1);

    for (int ch = 0; ch < 36; ch++) {
        int s = ch % R2_NSTG;
        if (ch + 1 < 36) CP_WAIT1(); else CP_WAIT0();
        __syncthreads();
        if (ch + 2 < 36) issue(ch + 2);

        uint32_t st = sb + s * R2_STG;
        int arow = m_base + (lane & 15);
        int acolx = (lane & 16);
        int brow = n_base + (lane & 7) + ((lane & 16) >> 1);
        int bcolx = (lane & 8) << 1;
#pragma unroll
        for (int ks = 0; ks < 4; ks++) {
            uint32_t aH[4][4], aL[4][4], bH[4][2], bL[4][2];
#pragma unroll
            for (int mf = 0; mf < 4; mf++) {
                uint32_t off = (uint32_t)(arow + mf * 16) * 128 + ks * 32 + acolx;
                off ^= (off >> 3) & 0x70;
                LDM_X4(aH[mf][0], aH[mf][1], aH[mf][2], aH[mf][3], st + R2_AH + off);
                LDM_X4(aL[mf][0], aL[mf][1], aL[mf][2], aL[mf][3], st + R2_AL + off);
            }
#pragma unroll
            for (int np = 0; np < 2; np++) {
                uint32_t off = (uint32_t)(brow + np * 16) * 128 + ks * 32 + bcolx;
                off ^= (off >> 3) & 0x70;
                uint32_t r0, r1, r2, r3;
                LDM_X4(r0, r1, r2, r3, st + R2_BH + off);
                bH[np * 2][0] = r0; bH[np * 2][1] = r1;
                bH[np * 2 + 1][0] = r2; bH[np * 2 + 1][1] = r3;
                LDM_X4(r0, r1, r2, r3, st + R2_BL + off);
                bL[np * 2][0] = r0; bL[np * 2][1] = r1;
                bL[np * 2 + 1][0] = r2; bL[np * 2 + 1][1] = r3;
            }
#pragma unroll
            for (int mf = 0; mf < 4; mf++)
#pragma unroll
                for (int nf = 0; nf < 4; nf++) {
                    MMA_BF16(acc[mf][nf], aH[mf], bH[nf][0], bH[nf][1]);
                    MMA_BF16(acc[mf][nf], aH[mf], bL[nf][0], bL[nf][1]);
                    MMA_BF16(acc[mf][nf], aL[mf], bH[nf][0], bH[nf][1]);
                }
        }
        __syncthreads();
    }

#pragma unroll
    for (int nf = 0; nf < 4; nf++) {
        int co = co0 + n_base + nf * 8 + (lane & 3) * 2;
        float bb0 = __ldg(bias + co), bb1 = __ldg(bias + co + 1);
        float* dst0 = outF + ((size_t)cam * 256 + co) * PIX;
        float* dst1 = dst0 + PIX;
#pragma unroll
        for (int mf = 0; mf < 4; mf++) {
            int pix = p0 + m_base + mf * 16 + (lane >> 2);
            if (pix < PIX) {
                dst0[pix] = eluf(acc[mf][nf][0] + bb0);
                dst1[pix] = eluf(acc[mf][nf][1] + bb1);
            }
            if (pix + 8 < PIX) {
                dst0[pix + 8] = eluf(acc[mf][nf][2] + bb0);
                dst1[pix + 8] = eluf(acc[mf][nf][3] + bb1);
            }
        }
    }
}

// ---------------- launch ----------------
extern "C" void kernel_launch(void* const* d_in, const int* in_sizes, int n_in,
                              void* d_out, int out_size) {
    const float* feats = (const float*)d_in[0];
    const float* masks = (const float*)d_in[1];
    const float* K     = (const float*)d_in[2];
    const float* ext   = (const float*)d_in[3];
    const float* w_ov  = (const float*)d_in[4];
    const float* b_ov  = (const float*)d_in[5];
    const float* w_no  = (const float*)d_in[6];
    const float* b_no  = (const float*)d_in[7];
    const float* w_fu  = (const float*)d_in[8];
    const float* b_fu  = (const float*)d_in[9];
    const float* w_r1  = (const float*)d_in[10];
    const float* b_r1  = (const float*)d_in[11];
    const float* w_r2  = (const float*)d_in[12];
    const float* b_r2  = (const float*)d_in[13];
    float* out = (float*)d_out;

    static cudaStream_t s2 = nullptr;
    static cudaEvent_t evRoot = nullptr, evFu = nullptr, evPrep = nullptr;
    if (!s2) {
        cudaStreamCreateWithFlags(&s2, cudaStreamNonBlocking);
        cudaEventCreateWithFlags(&evRoot, cudaEventDisableTiming);
        cudaEventCreateWithFlags(&evFu, cudaEventDisableTiming);
        cudaEventCreateWithFlags(&evPrep, cudaEventDisableTiming);
        cudaFuncSetAttribute(bpmlp_kernel, cudaFuncAttributeMaxDynamicSharedMemorySize, FUSED_SMEM);
        cudaFuncSetAttribute(conv_r1_sparse, cudaFuncAttributeMaxDynamicSharedMemorySize, R1_SMEM);
        cudaFuncSetAttribute(conv_r2_hmma, cudaFuncAttributeMaxDynamicSharedMemorySize, R2_SMEM);
        cudaFuncSetAttribute(conv3d_hmma, cudaFuncAttributeMaxDynamicSharedMemorySize, C3_SMEM);
    }

    // fork: weight prep on s2, overlapped with the voxel chain on stream 0
    cudaEventRecord(evRoot, 0);
    cudaStreamWaitEvent(s2, evRoot, 0);
    wprep_gen<<<256, 256, 0, s2>>>(w_fu, 2, 64, 128, 27);
    cudaEventRecord(evFu, s2);
    wprep_r1<<<2048, 256, 0, s2>>>(w_r1);
    wprep_gen<<<512, 256, 0, s2>>>(w_r2, 1, 256, 256, 9);
    cudaEventRecord(evPrep, s2);

    setup_kernel<<<1, 128>>>(K, ext);
    ftrans_kernel<<<(6 * 65 * PIX + 255) / 256, 256>>>(feats, masks);
    bpmlp_kernel<<<(NVOX + 127) / 128, 128, FUSED_SMEM>>>(w_ov, b_ov, w_no, b_no);
    remap_kernel<<<(NVOX + 3) / 4, 256>>>();
    cudaStreamWaitEvent(0, evFu, 0);
    conv3d_hmma<<<(NVOX + 127) / 128, 256, C3_SMEM>>>(b_fu);
    sample_kernel<<<dim3(110, DBINS, NCAM), 256>>>(ext);
    cudaStreamWaitEvent(0, evPrep, 0);
    conv_r1_sparse<<<dim3(28, 2, 6), 256, R1_SMEM>>>(b_r1);
    conv_r2_hmma<<<dim3(28, 2, 6), 256, R2_SMEM>>>(b_r2, out);
}

// round 16
// speedup vs baseline: 1.0088x; 1.0088x over previous
#include <cuda_runtime.h>
#include <cuda_bf16.h>
#include <math.h>
#include <stdint.h>

#define XDIM 100
#define YDIM 100
#define ZDIM 20
#define NVOX 200000
#define HF 44
#define WF 80
#define PIX 3520
#define NCAM 6
#define DBINS 50
#define KTOT1 28800   // 9 taps * 3200 ci (r1)
#define KTOT2 2304    // 9 taps * 256 ci  (r2)
#define KTOT3 3456    // 27 taps * 128 ci (fu)

// ---------------- scratch (static device allocations) ----------------
__device__ float g_ex[100];
__device__ float g_dbins[50];
__device__ float g_xi[100];
__device__ float g_M[6 * 16];
__device__ float g_K3inv[6 * 9];
__device__ unsigned long long g_bmask[6 * 110];  // per (cam, 32px-block): bit d = any in-grid sample

__device__ float g_fT[(size_t)6 * PIX * 65];   // feats+mask transposed: [cam][pix][c]
__device__ unsigned short g_vfh[(size_t)NVOX * 128];
__device__ unsigned short g_vfl[(size_t)NVOX * 128];
__device__ float g_vol[NVOX * 64];             // [z][y][x][c] fp32
__device__ unsigned short g_projh[(size_t)6 * PIX * 3200];
__device__ unsigned short g_projl[(size_t)6 * PIX * 3200];
__device__ unsigned short g_hbufh[(size_t)6 * PIX * 256];
__device__ unsigned short g_hbufl[(size_t)6 * PIX * 256];

__device__ unsigned short g_wr1h[(size_t)256 * KTOT1];
__device__ unsigned short g_wr1l[(size_t)256 * KTOT1];
__device__ unsigned short g_wr2h[(size_t)256 * KTOT2];
__device__ unsigned short g_wr2l[(size_t)256 * KTOT2];
__device__ unsigned short g_wfuh[(size_t)64 * KTOT3];
__device__ unsigned short g_wful[(size_t)64 * KTOT3];

__device__ __forceinline__ float eluf(float x) { return x > 0.f ? x : expm1f(x); }

__device__ __forceinline__ void split_bf16(float v, unsigned short& h, unsigned short& l) {
    __nv_bfloat16 bh = __float2bfloat16(v);
    float r = v - __bfloat162float(bh);
    __nv_bfloat16 bl = __float2bfloat16(r);
    h = *reinterpret_cast<unsigned short*>(&bh);
    l = *reinterpret_cast<unsigned short*>(&bl);
}
__device__ __forceinline__ float join_bf16(unsigned short h, unsigned short l) {
    __nv_bfloat16 bh = *reinterpret_cast<__nv_bfloat16*>(&h);
    __nv_bfloat16 bl = *reinterpret_cast<__nv_bfloat16*>(&l);
    return __bfloat162float(bh) + __bfloat162float(bl);
}

__device__ __forceinline__ uint32_t smem_u32(const void* p) {
    uint32_t a;
    asm("{ .reg .u64 t; cvta.to.shared.u64 t, %1; cvt.u32.u64 %0, t; }" : "=r"(a) : "l"(p));
    return a;
}
__device__ __forceinline__ void cp16(uint32_t dst, const void* src, int sz) {
    asm volatile("cp.async.cg.shared.global [%0], [%1], 16, %2;"
                 :: "r"(dst), "l"(src), "r"(sz) : "memory");
}
#define CP_COMMIT() asm volatile("cp.async.commit_group;" ::: "memory")
#define CP_WAIT1()  asm volatile("cp.async.wait_group 1;" ::: "memory")
#define CP_WAIT0()  asm volatile("cp.async.wait_group 0;" ::: "memory")

#define LDM_X4(r0, r1, r2, r3, addr) \
    asm volatile("ldmatrix.sync.aligned.m8n8.x4.shared.b16 {%0,%1,%2,%3}, [%4];" \
                 : "=r"(r0), "=r"(r1), "=r"(r2), "=r"(r3) : "r"(addr))

#define MMA_BF16(acc, a, b0v, b1v) \
    asm volatile("mma.sync.aligned.m16n8k16.row.col.f32.bf16.bf16.f32 " \
                 "{%0,%1,%2,%3}, {%4,%5,%6,%7}, {%8,%9}, {%0,%1,%2,%3};" \
                 : "+f"((acc)[0]), "+f"((acc)[1]), "+f"((acc)[2]), "+f"((acc)[3]) \
                 : "r"((a)[0]), "r"((a)[1]), "r"((a)[2]), "r"((a)[3]), "r"(b0v), "r"(b1v))

// ---------------- setup ----------------
__global__ void setup_kernel(const float* __restrict__ K, const float* __restrict__ ext) {
    int t = threadIdx.x;
    for (int i = t; i < 6 * 110; i += 128) g_bmask[i] = 0ull;
    if (t < 100) {
        double c0 = 1.0 / 51.5, c1 = 1.0 / 2.0;
        double lin = c0 + (double)(99 - t) * (c1 - c0) / 99.0;
        g_ex[t] = (float)(1.0 / lin);
    }
    if (t < 50) {
        double c0 = 1.0 / 50.0, c1 = 1.0 / 2.0;
        double lin = c0 + (double)(49 - t) * (c1 - c0) / 49.0;
        g_dbins[t] = (float)(1.0 / lin);
    }
    __syncthreads();
    if (t < 100) {
        float q = 2.0f + (float)t * (51.5f - 2.0f) / 99.0f;
        float qc = fminf(fmaxf(q, g_ex[0]), g_ex[99] - 1e-6f);
        int lo = 0, hi = 99;
        while (lo < hi) { int m = (lo + hi) >> 1; if (g_ex[m] >= qc) hi = m; else lo = m + 1; }
        int k = lo - 1; k = max(0, min(98, k));
        g_xi[t] = (float)k + (qc - g_ex[k]) / (g_ex[k + 1] - g_ex[k] + 1e-12f);
    }
    if (t < 6) {
        double A[4][8];
        for (int r = 0; r < 4; r++)
            for (int c = 0; c < 4; c++) {
                A[r][c] = (double)ext[t * 16 + r * 4 + c];
                A[r][c + 4] = (r == c) ? 1.0 : 0.0;
            }
        for (int col = 0; col < 4; col++) {
            int piv = col; double best = fabs(A[col][col]);
            for (int r = col + 1; r < 4; r++) { double v = fabs(A[r][col]); if (v > best) { best = v; piv = r; } }
            if (piv != col) for (int c = 0; c < 8; c++) { double tmp = A[col][c]; A[col][c] = A[piv][c]; A[piv][c] = tmp; }
            double d = A[col][col];
            for (int c = 0; c < 8; c++) A[col][c] /= d;
            for (int r = 0; r < 4; r++) if (r != col) {
                double f = A[r][col];
                for (int c = 0; c < 8; c++) A[r][c] -= f * A[col][c];
            }
        }
        for (int r = 0; r < 4; r++)
            for (int c = 0; c < 4; c++) {
                double s = 0;
                for (int k2 = 0; k2 < 4; k2++) s += (double)K[t * 16 + r * 4 + k2] * A[k2][c + 4];
                g_M[t * 16 + r * 4 + c] = (float)s;
            }
        double a00 = K[t*16+0], a01 = K[t*16+1], a02 = K[t*16+2];
        double a10 = K[t*16+4], a11 = K[t*16+5], a12 = K[t*16+6];
        double a20 = K[t*16+8], a21 = K[t*16+9], a22 = K[t*16+10];
        double det = a00*(a11*a22 - a12*a21) - a01*(a10*a22 - a12*a20) + a02*(a10*a21 - a11*a20);
        double id = 1.0 / det;
        g_K3inv[t*9+0] = (float)((a11*a22 - a12*a21) * id);
        g_K3inv[t*9+1] = (float)((a02*a21 - a01*a22) * id);
        g_K3inv[t*9+2] = (float)((a01*a12 - a02*a11) * id);
        g_K3inv[t*9+3] = (float)((a12*a20 - a10*a22) * id);
        g_K3inv[t*9+4] = (float)((a00*a22 - a02*a20) * id);
        g_K3inv[t*9+5] = (float)((a02*a10 - a00*a12) * id);
        g_K3inv[t*9+6] = (float)((a10*a21 - a11*a20) * id);
        g_K3inv[t*9+7] = (float)((a01*a20 - a00*a21) * id);
        g_K3inv[t*9+8] = (float)((a00*a11 - a01*a10) * id);
    }
}

// ---------------- feats transpose: [cam][c][pix] -> [cam][pix][65] ----------------
__global__ void ftrans_kernel(const float* __restrict__ feats, const float* __restrict__ masks) {
    int idx = blockIdx.x * blockDim.x + threadIdx.x;
    int total = 6 * 65 * PIX;
    if (idx >= total) return;
    int cam = idx / (65 * PIX);
    int r = idx % (65 * PIX);
    int c = r / PIX, p = r % PIX;
    float v = (c < 64) ? feats[(cam * 64 + c) * PIX + p] : masks[cam * PIX + p];
    g_fT[(size_t)(cam * PIX + p) * 65 + c] = v;
}

// ---------------- r1 weight prep ----------------
__global__ void wprep_r1(const float* __restrict__ w) {
    int total = 256 * 3200 * 9;
    for (int idx = blockIdx.x * blockDim.x + threadIdx.x; idx < total; idx += gridDim.x * blockDim.x) {
        int co = idx / (3200 * 9);
        int r = idx % (3200 * 9);
        int ci_ref = r / 9, tap = r % 9;
        int c = ci_ref / 50, d = ci_ref % 50;
        unsigned short h, l;
        split_bf16(w[idx], h, l);
        size_t dst = (size_t)co * KTOT1 + tap * 3200 + d * 64 + c;
        g_wr1h[dst] = h;
        g_wr1l[dst] = l;
    }
}

// ---------------- generic weight prep ----------------
__global__ void wprep_gen(const float* __restrict__ w, int which, int CO, int CI, int TAPS) {
    unsigned short* dh = (which == 1) ? g_wr2h : g_wfuh;
    unsigned short* dl = (which == 1) ? g_wr2l : g_wful;
    int KT = CI * TAPS;
    int total = CO * KT;
    for (int idx = blockIdx.x * blockDim.x + threadIdx.x; idx < total; idx += gridDim.x * blockDim.x) {
        int co = idx / KT;
        int r = idx % KT;
        int ci = r / TAPS, tap = r % TAPS;
        unsigned short h, l;
        split_bf16(w[idx], h, l);
        size_t dst = (size_t)co * KT + tap * CI + ci;
        dh[dst] = h;
        dl[dst] = l;
    }
}

// ---------------- fused backproj + voxel MLP ----------------
#define CAT_STRIDE 133
#define FUSED_SMEM 152616

__global__ __launch_bounds__(128) void bpmlp_kernel(const float* __restrict__ w_ov, const float* __restrict__ b_ov,
                                                    const float* __restrict__ w_no, const float* __restrict__ b_no) {
    extern __shared__ float sm[];
    float* wovS = sm;
    float* wnoS = wovS + 8320;
    float* catS = wnoS + 4160;
    int*   cntS = (int*)(catS + 130 * CAT_STRIDE);
    unsigned short* sh = (unsigned short*)(cntS + 128);
    unsigned short* sl = sh + 64 * 129;
    int t = threadIdx.x, lane = t & 31, w = t >> 5;
    int n0 = blockIdx.x * 128;

    for (int i = t; i < 8320; i += 128) wovS[i] = w_ov[i];
    for (int i = t; i < 4160; i += 128) wnoS[i] = w_no[i];

    for (int v = 0; v < 32; v++) {
        int col = w * 32 + v;
        int n = n0 + col;
        bool nv = n < NVOX;
        int ncl = nv ? n : 0;
        int z = ncl / 10000, y = (ncl / 100) % 100, x = ncl % 100;
        float gx = g_ex[x];
        float gy = -25.0f + 0.5f * (float)y;
        float gz = -3.0f + (float)z * (5.7f / 19.0f);
        float accg[2][3];
#pragma unroll
        for (int g2 = 0; g2 < 2; g2++)
#pragma unroll
            for (int j = 0; j < 3; j++) accg[g2][j] = 0.f;
        int cnt = 0;
#pragma unroll
        for (int cam = 0; cam < 6; cam++) {
            const float* Mc = &g_M[cam * 16];
            float px = Mc[0]*gx + Mc[1]*gy + Mc[2]*gz + Mc[3];
            float py = Mc[4]*gx + Mc[5]*gy + Mc[6]*gz + Mc[7];
            float pz = Mc[8]*gx + Mc[9]*gy + Mc[10]*gz + Mc[11];
            float zd = pz + 1e-8f;
            float u = px / zd, vv = py / zd;
            bool ok = (pz > 1e-8f) && (u >= 0.f) && (u <= 79.f) && (vv >= 0.f) && (vv <= 43.f);
            if (ok) {
                cnt++;
                float fu = floorf(u), fv = floorf(vv);
                float du = u - fu, dv = vv - fv;
                int u0 = min(max((int)fu, 0), 79); int u1 = min(u0 + 1, 79);
                int v0 = min(max((int)fv, 0), 43); int v1 = min(v0 + 1, 43);
                float w00 = (1 - du) * (1 - dv), w01 = du * (1 - dv);
                float w10 = (1 - du) * dv,       w11 = du * dv;
                const float* F = g_fT + (size_t)(cam * PIX) * 65;
                const float* F00 = F + (size_t)(v0 * 80 + u0) * 65;
                const float* F01 = F + (size_t)(v0 * 80 + u1) * 65;
                const float* F10 = F + (size_t)(v1 * 80 + u0) * 65;
                const float* F11 = F + (size_t)(v1 * 80 + u1) * 65;
                int g2 = cam >= 3;
#pragma unroll
                for (int j = 0; j < 3; j++) {
                    int c = j * 32 + lane;
                    if (c < 65) {
                        float val = w00 * __ldg(F00 + c) + w01 * __ldg(F01 + c)
                                  + w10 * __ldg(F10 + c) + w11 * __ldg(F11 + c);
                        accg[g2][j] += val;
                    }
                }
            }
        }
#pragma unroll
        for (int g2 = 0; g2 < 2; g2++)
#pragma unroll
            for (int j = 0; j < 3; j++) {
                int c = j * 32 + lane;
                if (c < 65) catS[(g2 * 65 + c) * CAT_STRIDE + col] = accg[g2][j];
            }
        if (lane == 0) cntS[col] = nv ? cnt : 0;
    }
    __syncthreads();

    int n = n0 + t;
    int cnt = cntS[t];
    if (cnt == 1 || cnt == 2) {
        float fo = (cnt == 2) ? 1.f : 0.f;
        float fn = (cnt == 1) ? 1.f : 0.f;
        for (int co = 0; co < 64; co++) {
            float av = b_ov[co], an = b_no[co];
            const float* wov = &wovS[co * 130];
            const float* wno = &wnoS[co * 65];
#pragma unroll 5
            for (int k = 0; k < 65; k++) {
                float cl = catS[k * CAT_STRIDE + t];
                float ch = catS[(k + 65) * CAT_STRIDE + t];
                av = fmaf(wov[k], cl, av);
                av = fmaf(wov[65 + k], ch, av);
                an = fmaf(wno[k], cl + ch, an);
            }
            float vv = fo * eluf(av) + fn * eluf(an);
            unsigned short h, l;
            split_bf16(vv, h, l);
            sh[co * 129 + t] = h;
            sl[co * 129 + t] = l;
        }
    } else {
        for (int co = 0; co < 64; co++) { sh[co * 129 + t] = 0; sl[co * 129 + t] = 0; }
    }
    __syncthreads();
    for (int i = t; i < 128 * 64; i += 128) {
        int v = i >> 6, c = i & 63;
        int nn = n0 + v;
        if (nn < NVOX) {
            size_t d = (size_t)nn * 128 + c;
            g_vfh[d] = sh[c * 129 + v];
            g_vfl[d] = sl[c * 129 + v];
        }
    }
}

// ---------------- x remap: fill c=64..127 of [voxel][c] ----------------
__global__ __launch_bounds__(256) void remap_kernel() {
    int t = threadIdx.x;
    int c = t & 63, vq = t >> 6;
    int n = blockIdx.x * 4 + vq;
    if (n >= NVOX) return;
    int x = n % 100;
    float xi = g_xi[x];
    float f = floorf(xi);
    float tx = xi - f;
    int a = min(max((int)f, 0), 99);
    int b2 = min(a + 1, 99);
    size_t rowbase = (size_t)(n - x) * 128;
    float va = join_bf16(g_vfh[rowbase + (size_t)a * 128 + c], g_vfl[rowbase + (size_t)a * 128 + c]);
    float vb = join_bf16(g_vfh[rowbase + (size_t)b2 * 128 + c], g_vfl[rowbase + (size_t)b2 * 128 + c]);
    float v = va * (1.f - tx) + vb * tx;
    unsigned short h, l;
    split_bf16(v, h, l);
    size_t d = (size_t)n * 128 + 64 + c;
    g_vfh[d] = h;
    g_vfl[d] = l;
}

// ---------------- conv3d HMMA: M=128 vox, N=64 co, K=3456 ----------------
#define C3_NSTG 3
#define C3_STG  49152
#define C3_AH   0
#define C3_AL   16384
#define C3_BH   32768
#define C3_BL   40960
#define C3_SMEM (C3_NSTG * C3_STG)

__global__ __launch_bounds__(256, 1) void conv3d_hmma(const float* __restrict__ bias) {
    extern __shared__ char smem[];
    uint32_t sb = smem_u32(smem);
    int t = threadIdx.x, lane = t & 31, wid = t >> 5;
    int n0 = blockIdx.x * 128;

    int rA = t & 127, half = t >> 7;
    int nA = n0 + rA;
    bool pvalid = nA < NVOX;
    int ncl = min(nA, NVOX - 1);
    int zA = ncl / 10000, yA = (ncl / 100) % 100, xA = ncl % 100;

    int rowB = t >> 2, jb = (t & 3) * 2;

    int wm = wid & 3, wn = wid >> 2;
    int m_base = wm * 32, n_base = wn * 32;

    float acc[2][4][4];
#pragma unroll
    for (int a = 0; a < 2; a++)
#pragma unroll
        for (int b = 0; b < 4; b++)
#pragma unroll
            for (int c = 0; c < 4; c++) acc[a][b][c] = 0.f;

    auto issue = [&](int ch) {
        int s = ch % C3_NSTG;
        uint32_t st = sb + s * C3_STG;
        int tap = ch >> 1, ci0 = (ch & 1) * 64;
        int dz = tap / 9 - 1, dy = (tap / 3) % 3 - 1, dx = tap % 3 - 1;
        int z2 = zA + dz, y2 = yA + dy, x2 = xA + dx;
        bool ok = pvalid && ((unsigned)z2 < 20u) && ((unsigned)y2 < 100u) && ((unsigned)x2 < 100u);
        size_t abase = ok ? ((size_t)((z2 * 100 + y2) * 100 + x2) * 128 + ci0 + half * 32)
                          : (size_t)(ci0 + half * 32);
        int sz = ok ? 16 : 0;
#pragma unroll
        for (int j = 0; j < 4; j++) {
            uint32_t off = (uint32_t)rA * 128 + half * 64 + j * 16;
            off ^= (off >> 3) & 0x70;
            cp16(st + C3_AH + off, g_vfh + abase + j * 8, sz);
            cp16(st + C3_AL + off, g_vfl + abase + j * 8, sz);
        }
        size_t bbase = (size_t)rowB * KTOT3 + tap * 128 + ci0;
#pragma unroll
        for (int jj = 0; jj < 2; jj++) {
            int j = jb + jj;
            uint32_t off = (uint32_t)rowB * 128 + j * 16;
            off ^= (off >> 3) & 0x70;
            cp16(st + C3_BH + off, g_wfuh + bbase + j * 8, 16);
            cp16(st + C3_BL + off, g_wful + bbase + j * 8, 16);
        }
        CP_COMMIT();
    };

    issue(0);
    issue(1);

    for (int ch = 0; ch < 54; ch++) {
        int s = ch % C3_NSTG;
        if (ch + 1 < 54) CP_WAIT1(); else CP_WAIT0();
        __syncthreads();
        if (ch + 2 < 54) issue(ch + 2);

        uint32_t st = sb + s * C3_STG;
        int arow = m_base + (lane & 15);
        int acolx = (lane & 16);
        int brow = n_base + (lane & 7) + ((lane & 16) >> 1);
        int bcolx = (lane & 8) << 1;
#pragma unroll
        for (int ks = 0; ks < 4; ks++) {
            uint32_t aH[2][4], aL[2][4], bH[4][2], bL[4][2];
#pragma unroll
            for (int mf = 0; mf < 2; mf++) {
                uint32_t off = (uint32_t)(arow + mf * 16) * 128 + ks * 32 + acolx;
                off ^= (off >> 3) & 0x70;
                LDM_X4(aH[mf][0], aH[mf][1], aH[mf][2], aH[mf][3], st + C3_AH + off);
                LDM_X4(aL[mf][0], aL[mf][1], aL[mf][2], aL[mf][3], st + C3_AL + off);
            }
#pragma unroll
            for (int np = 0; np < 2; np++) {
                uint32_t off = (uint32_t)(brow + np * 16) * 128 + ks * 32 + bcolx;
                off ^= (off >> 3) & 0x70;
                uint32_t r0, r1, r2, r3;
                LDM_X4(r0, r1, r2, r3, st + C3_BH + off);
                bH[np * 2][0] = r0; bH[np * 2][1] = r1;
                bH[np * 2 + 1][0] = r2; bH[np * 2 + 1][1] = r3;
                LDM_X4(r0, r1, r2, r3, st + C3_BL + off);
                bL[np * 2][0] = r0; bL[np * 2][1] = r1;
                bL[np * 2 + 1][0] = r2; bL[np * 2 + 1][1] = r3;
            }
#pragma unroll
            for (int mf = 0; mf < 2; mf++)
#pragma unroll
                for (int nf = 0; nf < 4; nf++) {
                    MMA_BF16(acc[mf][nf], aH[mf], bH[nf][0], bH[nf][1]);
                    MMA_BF16(acc[mf][nf], aH[mf], bL[nf][0], bL[nf][1]);
                    MMA_BF16(acc[mf][nf], aL[mf], bH[nf][0], bH[nf][1]);
                }
        }
        __syncthreads();
    }

#pragma unroll
    for (int nf = 0; nf < 4; nf++) {
        int c = n_base + nf * 8 + (lane & 3) * 2;
        float bb0 = __ldg(bias + c), bb1 = __ldg(bias + c + 1);
#pragma unroll
        for (int mf = 0; mf < 2; mf++) {
            int nn = n0 + m_base + mf * 16 + (lane >> 2);
            if (nn < NVOX) {
                g_vol[(size_t)nn * 64 + c] = eluf(acc[mf][nf][0] + bb0);
                g_vol[(size_t)nn * 64 + c + 1] = eluf(acc[mf][nf][1] + bb1);
            }
            if (nn + 8 < NVOX) {
                g_vol[(size_t)(nn + 8) * 64 + c] = eluf(acc[mf][nf][2] + bb0);
                g_vol[(size_t)(nn + 8) * 64 + c + 1] = eluf(acc[mf][nf][3] + bb1);
            }
        }
    }
}

// ---------------- frustum sampling (+ 32px-block occupancy mask) ----------------
__global__ __launch_bounds__(256) void sample_kernel(const float* __restrict__ ext) {
    __shared__ float exs[100];
    __shared__ int anyin;
    int t = threadIdx.x;
    if (t < 100) exs[t] = g_ex[t];
    if (t == 0) anyin = 0;
    __syncthreads();
    int cam = blockIdx.z, d = blockIdx.y, p0 = blockIdx.x * 32;
    int wrp = t >> 5, lane = t & 31;
    float dep = g_dbins[d];
    const float* Ki = &g_K3inv[cam * 9];
    const float* E = ext + cam * 16;
#pragma unroll
    for (int i = 0; i < 4; i++) {
        int p = p0 + wrp * 4 + i;
        float u = (float)(p % 80), v = (float)(p / 80);
        float cx = (Ki[0] * u + Ki[1] * v + Ki[2]) * dep;
        float cy = (Ki[3] * u + Ki[4] * v + Ki[5]) * dep;
        float cz = (Ki[6] * u + Ki[7] * v + Ki[8]) * dep;
        float wx = E[0] * cx + E[1] * cy + E[2] * cz + E[3];
        float wy = E[4] * cx + E[5] * cy + E[6] * cz + E[7];
        float wz = E[8] * cx + E[9] * cy + E[10] * cz + E[11];
        float yi = (wy - (-25.0f)) / 49.5f * 99.0f;
        float zi = (wz - (-3.0f)) / 5.7f * 19.0f;
        bool inb = (wx >= 2.0f) && (wx <= 51.5f) && (yi >= 0.f) && (yi <= 99.f) && (zi >= 0.f) && (zi <= 19.f);
        float v0 = 0.f, v1 = 0.f;
        if (inb) {
            if (lane == 0) anyin = 1;
            float qc = fminf(fmaxf(wx, exs[0]), exs[99] - 1e-6f);
            int lo = 0, hi = 99;
            while (lo < hi) { int m = (lo + hi) >> 1; if (exs[m] >= qc) hi = m; else lo = m + 1; }
            int k = max(0, min(98, lo - 1));
            float xi = (float)k + (qc - exs[k]) / (exs[k + 1] - exs[k] + 1e-12f);
            float fx = floorf(xi), fy = floorf(yi), fz = floorf(zi);
            float tx = xi - fx, ty = yi - fy, tz = zi - fz;
            int x0 = min(max((int)fx, 0), 99), x1 = min(x0 + 1, 99);
            int y0 = min(max((int)fy, 0), 99), y1 = min(y0 + 1, 99);
            int z0 = min(max((int)fz, 0), 19), z1 = min(z0 + 1, 19);
            float w000 = (1 - tx) * (1 - ty) * (1 - tz), w100 = tx * (1 - ty) * (1 - tz);
            float w010 = (1 - tx) * ty * (1 - tz),       w110 = tx * ty * (1 - tz);
            float w001 = (1 - tx) * (1 - ty) * tz,       w101 = tx * (1 - ty) * tz;
            float w011 = (1 - tx) * ty * tz,             w111 = tx * ty * tz;
            int b000 = ((z0 * 100 + y0) * 100 + x0) * 64;
            int b100 = ((z0 * 100 + y0) * 100 + x1) * 64;
            int b010 = ((z0 * 100 + y1) * 100 + x0) * 64;
            int b110 = ((z0 * 100 + y1) * 100 + x1) * 64;
            int b001 = ((z1 * 100 + y0) * 100 + x0) * 64;
            int b101 = ((z1 * 100 + y0) * 100 + x1) * 64;
            int b011 = ((z1 * 100 + y1) * 100 + x0) * 64;
            int b111 = ((z1 * 100 + y1) * 100 + x1) * 64;
            const float* V = g_vol;
            v0 = w000 * V[b000 + lane] + w100 * V[b100 + lane]
               + w010 * V[b010 + lane] + w110 * V[b110 + lane]
               + w001 * V[b001 + lane] + w101 * V[b101 + lane]
               + w011 * V[b011 + lane] + w111 * V[b111 + lane];
            int l2 = lane + 32;
            v1 = w000 * V[b000 + l2] + w100 * V[b100 + l2]
               + w010 * V[b010 + l2] + w110 * V[b110 + l2]
               + w001 * V[b001 + l2] + w101 * V[b101 + l2]
               + w011 * V[b011 + l2] + w111 * V[b111 + l2];
        }
        unsigned short h0, l0, h1, l1;
        split_bf16(v0, h0, l0);
        split_bf16(v1, h1, l1);
        size_t base = ((size_t)(cam * PIX + p)) * 3200 + (size_t)d * 64;
        g_projh[base + lane] = h0;        g_projl[base + lane] = l0;
        g_projh[base + 32 + lane] = h1;   g_projl[base + 32 + lane] = l1;
    }
    __syncthreads();
    if (t == 0 && anyin)
        atomicOr(&g_bmask[cam * 110 + blockIdx.x], 1ull << d);
}

// ---------------- conv r1 HMMA: M=64 pix x N=128 co, per-tap-row sparse d-lists ----------------
#define R1_NSTG 3
#define R1_STG  49152
#define R1_AH   0
#define R1_AL   8192
#define R1_BH   16384
#define R1_BL   32768
#define R1_SMEM (R1_NSTG * R1_STG)

__global__ __launch_bounds__(256, 1) void conv_r1_sparse(const float* __restrict__ bias) {
    extern __shared__ char smem[];
    __shared__ unsigned char dlist3[3][56];
    __shared__ int dcnt3[3];
    uint32_t sb = smem_u32(smem);
    int t = threadIdx.x, lane = t & 31, wid = t >> 5;
    int cam = blockIdx.z;
    int co0 = blockIdx.y * 128;
    int p0 = blockIdx.x * 64;

    if (t < 3) {
        int dy = t - 1;
        int rowlo = p0 + dy * 80 - 1;
        int rowhi = p0 + 63 + dy * 80 + 1;
        int c = 0;
        if (rowhi >= 0 && rowlo < PIX) {
            int blo = max(0, rowlo) >> 5;
            int bhi = min(PIX - 1, rowhi) >> 5;
            unsigned long long m = 0ull;
            for (int b = blo; b <= bhi; b++) m |= g_bmask[cam * 110 + b];
            for (int d = 0; d < 50; d++)
                if ((m >> d) & 1) dlist3[t][c++] = (unsigned char)d;
        }
        dcnt3[t] = c;
    }
    __syncthreads();
    int cnt0 = dcnt3[0], cnt1 = dcnt3[1], cnt2 = dcnt3[2];
    int b0 = cnt0 * 3, b1 = b0 + cnt1 * 3;
    int nact = b1 + cnt2 * 3;

    const unsigned short* inH = g_projh + (size_t)cam * PIX * 3200;
    const unsigned short* inL = g_projl + (size_t)cam * PIX * 3200;

    // A loader: row = t&63, quarter q = t>>6 (16 ci elements each, 2x cp16)
    int rowA = t & 63, qA = t >> 6;
    int pA = p0 + rowA;
    int ypix = pA / 80, xpix = pA % 80;
    // B loader: row = t&127, half = t>>7 (32 ci elements, 4x cp16)
    int rowB = t & 127, halfB = t >> 7;

    int wm = wid & 1, wn = wid >> 1;
    int m_base = wm * 32, n_base = wn * 32;

    float acc[2][4][4];
#pragma unroll
    for (int a = 0; a < 2; a++)
#pragma unroll
        for (int b = 0; b < 4; b++)
#pragma unroll
            for (int c = 0; c < 4; c++) acc[a][b][c] = 0.f;

    auto issue = [&](int li) {
        int s = li % R1_NSTG;
        uint32_t st = sb + s * R1_STG;
        // per-tap-row groups; within a group: d-outer / x-tap-inner (3 taps share proj rows)
        int dyi, local;
        if (li < b0) { dyi = 0; local = li; }
        else if (li < b1) { dyi = 1; local = li - b0; }
        else { dyi = 2; local = li - b1; }
        int di = local / 3;
        int txp = local - di * 3;
        int dd = dlist3[dyi][di];
        int ci0 = dd * 64;
        int tap = dyi * 3 + txp;
        int dy = dyi - 1, dx = txp - 1;
        int y2 = ypix + dy, x2 = xpix + dx;
        bool ok = ((unsigned)y2 < 44u) && ((unsigned)x2 < 80u);
        size_t abase = ok ? (((size_t)(y2 * 80 + x2)) * 3200 + ci0 + qA * 16)
                          : (size_t)(ci0 + qA * 16);
        int sz = ok ? 16 : 0;
#pragma unroll
        for (int j = 0; j < 2; j++) {
            uint32_t off = (uint32_t)rowA * 128 + qA * 32 + j * 16;
            off ^= (off >> 3) & 0x70;
            cp16(st + R1_AH + off, inH + abase + j * 8, sz);
            cp16(st + R1_AL + off, inL + abase + j * 8, sz);
        }
        size_t bbase = (size_t)(co0 + rowB) * KTOT1 + tap * 3200 + ci0 + halfB * 32;
#pragma unroll
        for (int j = 0; j < 4; j++) {
            uint32_t off = (uint32_t)rowB * 128 + halfB * 64 + j * 16;
            off ^= (off >> 3) & 0x70;
            cp16(st + R1_BH + off, g_wr1h + bbase + j * 8, 16);
            cp16(st + R1_BL + off, g_wr1l + bbase + j * 8, 16);
        }
        CP_COMMIT();
    };

    if (nact > 0) issue(0);
    if (nact > 1) issue(1);

    for (int ch = 0; ch < nact; ch++) {
        int s = ch % R1_NSTG;
        if (ch + 1 < nact) CP_WAIT1(); else CP_WAIT0();
        __syncthreads();
        if (ch + 2 < nact) issue(ch + 2);

        uint32_t st = sb + s * R1_STG;
        int arow = m_base + (lane & 15);
        int acolx = (lane & 16);
        int brow = n_base + (lane & 7) + ((lane & 16) >> 1);
        int bcolx = (lane & 8) << 1;
#pragma unroll
        for (int ks = 0; ks < 4; ks++) {
            uint32_t aH[2][4], aL[2][4], bH[4][2], bL[4][2];
#pragma unroll
            for (int mf = 0; mf < 2; mf++) {
                uint32_t off = (uint32_t)(arow + mf * 16) * 128 + ks * 32 + acolx;
                off ^= (off >> 3) & 0x70;
                LDM_X4(aH[mf][0], aH[mf][1], aH[mf][2], aH[mf][3], st + R1_AH + off);
                LDM_X4(aL[mf][0], aL[mf][1], aL[mf][2], aL[mf][3], st + R1_AL + off);
            }
#pragma unroll
            for (int np = 0; np < 2; np++) {
                uint32_t off = (uint32_t)(brow + np * 16) * 128 + ks * 32 + bcolx;
                off ^= (off >> 3) & 0x70;
                uint32_t r0, r1, r2, r3;
                LDM_X4(r0, r1, r2, r3, st + R1_BH + off);
                bH[np * 2][0] = r0; bH[np * 2][1] = r1;
                bH[np * 2 + 1][0] = r2; bH[np * 2 + 1][1] = r3;
                LDM_X4(r0, r1, r2, r3, st + R1_BL + off);
                bL[np * 2][0] = r0; bL[np * 2][1] = r1;
                bL[np * 2 + 1][0] = r2; bL[np * 2 + 1][1] = r3;
            }
#pragma unroll
            for (int mf = 0; mf < 2; mf++)
#pragma unroll
                for (int nf = 0; nf < 4; nf++) {
                    MMA_BF16(acc[mf][nf], aH[mf], bH[nf][0], bH[nf][1]);
                    MMA_BF16(acc[mf][nf], aH[mf], bL[nf][0], bL[nf][1]);
                    MMA_BF16(acc[mf][nf], aL[mf], bH[nf][0], bH[nf][1]);
                }
        }
        __syncthreads();
    }

    // epilogue: bias + elu -> bf16 hi/lo hbuf [cam][pix][co]
#pragma unroll
    for (int nf = 0; nf < 4; nf++) {
        int co = co0 + n_base + nf * 8 + (lane & 3) * 2;
        float bb0 = __ldg(bias + co), bb1 = __ldg(bias + co + 1);
#pragma unroll
        for (int mf = 0; mf < 2; mf++) {
            int pix = p0 + m_base + mf * 16 + (lane >> 2);
#pragma unroll
            for (int q = 0; q < 2; q++) {
                int px = pix + q * 8;
                float v0 = eluf(acc[mf][nf][q * 2] + bb0);
                float v1 = eluf(acc[mf][nf][q * 2 + 1] + bb1);
                unsigned short h0, l0, h1, l1;
                split_bf16(v0, h0, l0);
                split_bf16(v1, h1, l1);
                size_t d = ((size_t)cam * PIX + px) * 256 + co;
                *reinterpret_cast<ushort2*>(&g_hbufh[d]) = make_ushort2(h0, h1);
                *reinterpret_cast<ushort2*>(&g_hbufl[d]) = make_ushort2(l0, l1);
            }
        }
    }
}

// ---------------- conv r2 HMMA: M=128 pix x N=128 co, dense, fp32 out ----------------
#define R2_NSTG 3
#define R2_STG  65536
#define R2_AH   0
#define R2_AL   16384
#define R2_BH   32768
#define R2_BL   49152
#define R2_SMEM (R2_NSTG * R2_STG)

__global__ __launch_bounds__(256, 1) void conv_r2_hmma(const float* __restrict__ bias, float* __restrict__ outF) {
    extern __shared__ char smem[];
    uint32_t sb = smem_u32(smem);
    int t = threadIdx.x, lane = t & 31, wid = t >> 5;
    int cam = blockIdx.z;
    int co0 = blockIdx.y * 128;
    int p0 = blockIdx.x * 128;

    const unsigned short* inH = g_hbufh + (size_t)cam * PIX * 256;
    const unsigned short* inL = g_hbufl + (size_t)cam * PIX * 256;

    int rA = t & 127, half = t >> 7;
    int pA = p0 + rA;
    int ypix = pA / 80, xpix = pA % 80;
    bool pvalid = pA < PIX;

    int wm = wid & 1, wn = wid >> 1;
    int m_base = wm * 64, n_base = wn * 32;

    float acc[4][4][4];
#pragma unroll
    for (int a = 0; a < 4; a++)
#pragma unroll
        for (int b = 0; b < 4; b++)
#pragma unroll
            for (int c = 0; c < 4; c++) acc[a][b][c] = 0.f;

    auto issue = [&](int ch) {
        int s = ch % R2_NSTG;
        uint32_t st = sb + s * R2_STG;
        int tap = ch >> 2, ci0 = (ch & 3) * 64;
        int dy = tap / 3 - 1, dx = tap % 3 - 1;
        int y2 = ypix + dy, x2 = xpix + dx;
        bool ok = pvalid && ((unsigned)y2 < 44u) && ((unsigned)x2 < 80u);
        size_t abase = ok ? (((size_t)(y2 * 80 + x2)) * 256 + ci0 + half * 32)
                          : (size_t)(ci0 + half * 32);
        int sz = ok ? 16 : 0;
#pragma unroll
        for (int j = 0; j < 4; j++) {
            uint32_t off = (uint32_t)rA * 128 + half * 64 + j * 16;
            off ^= (off >> 3) & 0x70;
            cp16(st + R2_AH + off, inH + abase + j * 8, sz);
            cp16(st + R2_AL + off, inL + abase + j * 8, sz);
        }
        size_t bbase = (size_t)(co0 + rA) * KTOT2 + tap * 256 + ci0 + half * 32;
#pragma unroll
        for (int j = 0; j < 4; j++) {
            uint32_t off = (uint32_t)rA * 128 + half * 64 + j * 16;
            off ^= (off >> 3) & 0x70;
            cp16(st + R2_BH + off, g_wr2h + bbase + j * 8, 16);
            cp16(st + R2_BL + off, g_wr2l + bbase + j * 8, 16);
        }
        CP_COMMIT();
    };

    issue(0);
    issue(1);

    for (int ch = 0; ch < 36; ch++) {
        int s = ch % R2_NSTG;
        if (ch + 1 < 36) CP_WAIT1(); else CP_WAIT0();
        __syncthreads();
        if (ch + 2 < 36) issue(ch + 2);

        uint32_t st = sb + s * R2_STG;
        int arow = m_base + (lane & 15);
        int acolx = (lane & 16);
        int brow = n_base + (lane & 7) + ((lane & 16) >> 1);
        int bcolx = (lane & 8) << 1;
#pragma unroll
        for (int ks = 0; ks < 4; ks++) {
            uint32_t aH[4][4], aL[4][4], bH[4][2], bL[4][2];
#pragma unroll
            for (int mf = 0; mf < 4; mf++) {
                uint32_t off = (uint32_t)(arow + mf * 16) * 128 + ks * 32 + acolx;
                off ^= (off >> 3) & 0x70;
                LDM_X4(aH[mf][0], aH[mf][1], aH[mf][2], aH[mf][3], st + R2_AH + off);
                LDM_X4(aL[mf][0], aL[mf][1], aL[mf][2], aL[mf][3], st + R2_AL + off);
            }
#pragma unroll
            for (int np = 0; np < 2; np++) {
                uint32_t off = (uint32_t)(brow + np * 16) * 128 + ks * 32 + bcolx;
                off ^= (off >> 3) & 0x70;
                uint32_t r0, r1, r2, r3;
                LDM_X4(r0, r1, r2, r3, st + R2_BH + off);
                bH[np * 2][0] = r0; bH[np * 2][1] = r1;
                bH[np * 2 + 1][0] = r2; bH[np * 2 + 1][1] = r3;
                LDM_X4(r0, r1, r2, r3, st + R2_BL + off);
                bL[np * 2][0] = r0; bL[np * 2][1] = r1;
                bL[np * 2 + 1][0] = r2; bL[np * 2 + 1][1] = r3;
            }
#pragma unroll
            for (int mf = 0; mf < 4; mf++)
#pragma unroll
                for (int nf = 0; nf < 4; nf++) {
                    MMA_BF16(acc[mf][nf], aH[mf], bH[nf][0], bH[nf][1]);
                    MMA_BF16(acc[mf][nf], aH[mf], bL[nf][0], bL[nf][1]);
                    MMA_BF16(acc[mf][nf], aL[mf], bH[nf][0], bH[nf][1]);
                }
        }
        __syncthreads();
    }

#pragma unroll
    for (int nf = 0; nf < 4; nf++) {
        int co = co0 + n_base + nf * 8 + (lane & 3) * 2;
        float bb0 = __ldg(bias + co), bb1 = __ldg(bias + co + 1);
        float* dst0 = outF + ((size_t)cam * 256 + co) * PIX;
        float* dst1 = dst0 + PIX;
#pragma unroll
        for (int mf = 0; mf < 4; mf++) {
            int pix = p0 + m_base + mf * 16 + (lane >> 2);
            if (pix < PIX) {
                dst0[pix] = eluf(acc[mf][nf][0] + bb0);
                dst1[pix] = eluf(acc[mf][nf][1] + bb1);
            }
            if (pix + 8 < PIX) {
                dst0[pix + 8] = eluf(acc[mf][nf][2] + bb0);
                dst1[pix + 8] = eluf(acc[mf][nf][3] + bb1);
            }
        }
    }
}

// ---------------- launch ----------------
extern "C" void kernel_launch(void* const* d_in, const int* in_sizes, int n_in,
                              void* d_out, int out_size) {
    const float* feats = (const float*)d_in[0];
    const float* masks = (const float*)d_in[1];
    const float* K     = (const float*)d_in[2];
    const float* ext   = (const float*)d_in[3];
    const float* w_ov  = (const float*)d_in[4];
    const float* b_ov  = (const float*)d_in[5];
    const float* w_no  = (const float*)d_in[6];
    const float* b_no  = (const float*)d_in[7];
    const float* w_fu  = (const float*)d_in[8];
    const float* b_fu  = (const float*)d_in[9];
    const float* w_r1  = (const float*)d_in[10];
    const float* b_r1  = (const float*)d_in[11];
    const float* w_r2  = (const float*)d_in[12];
    const float* b_r2  = (const float*)d_in[13];
    float* out = (float*)d_out;

    static cudaStream_t s2 = nullptr;
    static cudaEvent_t evRoot = nullptr, evFu = nullptr, evPrep = nullptr;
    if (!s2) {
        cudaStreamCreateWithFlags(&s2, cudaStreamNonBlocking);
        cudaEventCreateWithFlags(&evRoot, cudaEventDisableTiming);
        cudaEventCreateWithFlags(&evFu, cudaEventDisableTiming);
        cudaEventCreateWithFlags(&evPrep, cudaEventDisableTiming);
        cudaFuncSetAttribute(bpmlp_kernel, cudaFuncAttributeMaxDynamicSharedMemorySize, FUSED_SMEM);
        cudaFuncSetAttribute(conv_r1_sparse, cudaFuncAttributeMaxDynamicSharedMemorySize, R1_SMEM);
        cudaFuncSetAttribute(conv_r2_hmma, cudaFuncAttributeMaxDynamicSharedMemorySize, R2_SMEM);
        cudaFuncSetAttribute(conv3d_hmma, cudaFuncAttributeMaxDynamicSharedMemorySize, C3_SMEM);
    }

    // fork: weight prep on s2, overlapped with the voxel chain on stream 0
    cudaEventRecord(evRoot, 0);
    cudaStreamWaitEvent(s2, evRoot, 0);
    wprep_gen<<<256, 256, 0, s2>>>(w_fu, 2, 64, 128, 27);
    cudaEventRecord(evFu, s2);
    wprep_r1<<<2048, 256, 0, s2>>>(w_r1);
    wprep_gen<<<512, 256, 0, s2>>>(w_r2, 1, 256, 256, 9);
    cudaEventRecord(evPrep, s2);

    setup_kernel<<<1, 128>>>(K, ext);
    ftrans_kernel<<<(6 * 65 * PIX + 255) / 256, 256>>>(feats, masks);
    bpmlp_kernel<<<(NVOX + 127) / 128, 128, FUSED_SMEM>>>(w_ov, b_ov, w_no, b_no);
    remap_kernel<<<(NVOX + 3) / 4, 256>>>();
    cudaStreamWaitEvent(0, evFu, 0);
    conv3d_hmma<<<(NVOX + 127) / 128, 256, C3_SMEM>>>(b_fu);
    sample_kernel<<<dim3(110, DBINS, NCAM), 256>>>(ext);
    cudaStreamWaitEvent(0, evPrep, 0);
    conv_r1_sparse<<<dim3(PIX / 64, 2, 6), 256, R1_SMEM>>>(b_r1);
    conv_r2_hmma<<<dim3(28, 2, 6), 256, R2_SMEM>>>(b_r2, out);
}